// round 9
// baseline (speedup 1.0000x reference)
#include <cuda_runtime.h>

// T=2048, B=1024, H=50, 4H=200. Only batch row B-1 reaches the output
// (reference takes hs[:, -1, :] on the batch axis) and the recurrence is
// batch-independent -> single length-2048 sequence, H=50, on ONE SM.
#define TT 2048
#define BB 1024
#define HH 50
#define NTHREADS 256  // 8 warps (2/SMSP). Lane quad 4u..4u+3 owns unit u:
                      // q0: rows(i,g) x h[0:26)   q1: rows(i,g) x h[26:50)
                      // q2: rows(f,o) x h[0:26)   q3: rows(f,o) x h[26:50)

// Per-timestep hidden history; output dot handled in parallel epilogue.
__device__ float g_hs[TT * HH];

typedef unsigned long long ull;

__device__ __forceinline__ ull ffma2(ull a, ull b, ull c) {
    ull d;
    asm("fma.rn.f32x2 %0, %1, %2, %3;" : "=l"(d) : "l"(a), "l"(b), "l"(c));
    return d;
}
__device__ __forceinline__ ull fadd2(ull a, ull b) {
    ull d;
    asm("add.rn.f32x2 %0, %1, %2;" : "=l"(d) : "l"(a), "l"(b));
    return d;
}
__device__ __forceinline__ float tanh_fast(float x) {
    float r;
    asm("tanh.approx.f32 %0, %1;" : "=f"(r) : "f"(x));
    return r;
}
__device__ __forceinline__ float f2lo(ull v) { union { ull u; float2 f; } w; w.u = v; return w.f.x; }
__device__ __forceinline__ float f2hi(ull v) { union { ull u; float2 f; } w; w.u = v; return w.f.y; }
__device__ __forceinline__ ull pack2(float a, float b) {
    union { ull u; float2 f; } w; w.f.x = a; w.f.y = b; return w.u;
}

__global__ __launch_bounds__(NTHREADS, 1)
void lstm_seq_kernel(const float* __restrict__ x,      // (T, B, 1)
                     const float* __restrict__ W_ih,   // (4H, 1)
                     const float* __restrict__ W_hh,   // (4H, H)
                     const float* __restrict__ b_ih,
                     const float* __restrict__ b_hh,
                     const float* __restrict__ W_lin,  // (1, H)
                     const float* __restrict__ b_lin,
                     float* __restrict__ out)          // T floats
{
    __shared__ __align__(16) float h_s[2][56];  // double buffer; [50..55] stay 0
    __shared__ float xcol[TT];

    const int j      = threadIdx.x;
    const int q      = j & 3;        // quad role
    const int halfAB = q >> 1;       // 0: rows (i,g)   1: rows (f,o)
    const int hh     = q & 1;        // 0: h[0:26)      1: h[26:50)+pad
    const int u      = j >> 2;       // unit 0..63 (>=50 redundant)
    const int uc     = (u < HH) ? u : (HH - 1);
    const int rowA   = halfAB ? (HH + uc)     : uc;           // f : i
    const int rowB   = halfAB ? (3 * HH + uc) : (2 * HH + uc);// o : g
    const int koff   = hh * 13;      // packed-pair offset into h

    for (int t = j; t < TT; t += NTHREADS) xcol[t] = x[t * BB + (BB - 1)];
    if (j < 56) { h_s[0][j] = 0.0f; h_s[1][j] = 0.0f; }

    // 13 packed weight pairs per row-half; pair index 25 (beyond H=50) -> 0.
    ull wpA[13], wpB[13];
    {
        const ull* ra = reinterpret_cast<const ull*>(W_hh + rowA * HH);
        const ull* rb = reinterpret_cast<const ull*>(W_hh + rowB * HH);
        #pragma unroll
        for (int k = 0; k < 13; k++) {
            int pi = koff + k;
            bool v = (pi < 25);
            wpA[k] = v ? ra[pi] : 0ull;
            wpB[k] = v ? rb[pi] : 0ull;
        }
    }
    const float bsumA = b_ih[rowA] + b_hh[rowA];
    const float bsumB = b_ih[rowB] + b_hh[rowB];
    const float wihA  = W_ih[rowA];
    const float wihB  = W_ih[rowB];
    // rowA is always sigmoid; rowB: tanh on (i,g) lanes, sigmoid on (f,o) lanes
    const float ascB  = halfAB ? 0.5f : 1.0f;
    const float amulB = halfAB ? 0.5f : 1.0f;
    const float aaddB = halfAB ? 0.5f : 0.0f;

    float c = 0.0f;                  // live on q2/q3 lanes (redundant pair)
    __syncthreads();

    #pragma unroll 1
    for (int t2 = 0; t2 < TT; t2 += 2) {
        #pragma unroll
        for (int s = 0; s < 2; s++) {
            const int t = t2 + s;
            const float* hsrc = h_s[s];
            float*       hdst = h_s[s ^ 1];
            const float  xv   = xcol[t];
            const float preA0 = fmaf(xv, wihA, bsumA);
            const float preB0 = fmaf(xv, wihB, bsumB);

            // --- half-dots: 13 packed FMAs per row, 2 accumulators ---
            ull aA0 = 0ull, aA1 = 0ull, aB0 = 0ull, aB1 = 0ull;
            const ull* h2 = reinterpret_cast<const ull*>(hsrc) + koff;
            #pragma unroll
            for (int k = 0; k < 12; k += 2) {
                ull p0 = h2[k];
                ull p1 = h2[k + 1];
                aA0 = ffma2(wpA[k],     p0, aA0);
                aA1 = ffma2(wpA[k + 1], p1, aA1);
                aB0 = ffma2(wpB[k],     p0, aB0);
                aB1 = ffma2(wpB[k + 1], p1, aB1);
            }
            {
                ull pl = h2[12];
                aA0 = ffma2(wpA[12], pl, aA0);
                aB0 = ffma2(wpB[12], pl, aB0);
            }
            ull rA = fadd2(aA0, aA1);
            ull rB = fadd2(aB0, aB1);
            float sA = f2lo(rA) + f2hi(rA);
            float sB = f2lo(rB) + f2hi(rB);

            // --- cross-half reduce (xor 1), deterministic low+high order ---
            ull mypk = pack2(sA, sB);
            ull otpk = __shfl_xor_sync(0xffffffffu, mypk, 1, 32);
            ull lowp  = hh ? otpk : mypk;
            ull highp = hh ? mypk : otpk;
            float preA = preA0 + (f2lo(lowp) + f2lo(highp));
            float preB = preB0 + (f2hi(lowp) + f2hi(highp));

            // --- activations ---
            float aAv = fmaf(tanh_fast(preA * 0.5f), 0.5f, 0.5f);     // i / f
            float aBv = fmaf(tanh_fast(preB * ascB), amulB, aaddB);   // g / o

            // --- ship p = i*g from (i,g) lanes to (f,o) lanes (xor 2) ---
            float pv  = aAv * aBv;            // meaningful on q0/q1
            float got = __shfl_xor_sync(0xffffffffu, pv, 2, 32);

            if (halfAB) {                      // q2/q3 own c (identical values)
                c = fmaf(aAv, c, got);         // c = f*c + i*g
                float hn = aBv * tanh_fast(c); // h = o*tanh(c)
                if (q == 2 && u < HH) {
                    hdst[u] = hn;
                    g_hs[t * HH + u] = hn;     // fire-and-forget for epilogue
                }
            }
            __syncthreads();
        }
    }

    // Epilogue: out[t] = dot(h_t, W_lin) + b_lin, parallel over t.
    const float bl = b_lin[0];
    for (int t = j; t < TT; t += NTHREADS) {
        float s = bl;
        #pragma unroll
        for (int k = 0; k < HH; k++) s += g_hs[t * HH + k] * W_lin[k];
        out[t] = s;
    }
}

extern "C" void kernel_launch(void* const* d_in, const int* in_sizes, int n_in,
                              void* d_out, int out_size) {
    const float* x     = (const float*)d_in[0];
    const float* W_ih  = (const float*)d_in[1];
    const float* W_hh  = (const float*)d_in[2];
    const float* b_ih  = (const float*)d_in[3];
    const float* b_hh  = (const float*)d_in[4];
    const float* W_lin = (const float*)d_in[5];
    const float* b_lin = (const float*)d_in[6];
    lstm_seq_kernel<<<1, NTHREADS>>>(x, W_ih, W_hh, b_ih, b_hh, W_lin, b_lin,
                                     (float*)d_out);
}

// round 10
// speedup vs baseline: 1.1016x; 1.1016x over previous
#include <cuda_runtime.h>

// T=2048, B=1024, H=50, 4H=200. Only batch row B-1 reaches the output
// (reference takes hs[:, -1, :] on the batch axis) and the recurrence is
// batch-independent -> single length-2048 sequence, H=50, on ONE SM.
#define TT 2048
#define BB 1024
#define HH 50
#define NTHREADS 128   // 4 warps, 1 per SMSP; lane pair 2u/2u+1 owns unit u

// Per-timestep hidden history; output dot handled in parallel epilogue.
__device__ float g_hs[TT * HH];

typedef unsigned long long ull;

__device__ __forceinline__ ull ffma2(ull a, ull b, ull c) {
    ull d;
    asm("fma.rn.f32x2 %0, %1, %2, %3;" : "=l"(d) : "l"(a), "l"(b), "l"(c));
    return d;
}
__device__ __forceinline__ ull fadd2(ull a, ull b) {
    ull d;
    asm("add.rn.f32x2 %0, %1, %2;" : "=l"(d) : "l"(a), "l"(b));
    return d;
}
__device__ __forceinline__ ull fmul2(ull a, ull b) {
    ull d;
    asm("mul.rn.f32x2 %0, %1, %2;" : "=l"(d) : "l"(a), "l"(b));
    return d;
}
__device__ __forceinline__ float tanh_fast(float x) {
    float r;
    asm("tanh.approx.f32 %0, %1;" : "=f"(r) : "f"(x));
    return r;
}
__device__ __forceinline__ float f2lo(ull v) { union { ull u; float2 f; } w; w.u = v; return w.f.x; }
__device__ __forceinline__ float f2hi(ull v) { union { ull u; float2 f; } w; w.u = v; return w.f.y; }
__device__ __forceinline__ ull pack2(float a, float b) {
    union { ull u; float2 f; } w; w.f.x = a; w.f.y = b; return w.u;
}

__global__ __launch_bounds__(NTHREADS, 1)
void lstm_seq_kernel(const float* __restrict__ x,      // (T, B, 1)
                     const float* __restrict__ W_ih,   // (4H, 1)
                     const float* __restrict__ W_hh,   // (4H, H)
                     const float* __restrict__ b_ih,
                     const float* __restrict__ b_hh,
                     const float* __restrict__ W_lin,  // (1, H)
                     const float* __restrict__ b_lin,
                     float* __restrict__ out)          // T floats
{
    __shared__ __align__(16) float h_s[2][56];  // double buffer
    __shared__ float xcol[TT];

    const int j    = threadIdx.x;
    const int lane = j & 31;
    const int half = j & 1;                 // 0: gates (i,g)   1: gates (f,o)
    const int u    = j >> 1;                // unit 0..63 (>=50 redundant)
    const int uc   = (u < HH) ? u : (HH - 1);
    // rowA: i (even) / f (odd) -- always sigmoid
    // rowB: g (even, tanh) / o (odd, sigmoid)
    const int rowA = half ? (HH + uc)     : uc;
    const int rowB = half ? (3 * HH + uc) : (2 * HH + uc);

    for (int t = j; t < TT; t += NTHREADS) xcol[t] = x[t * BB + (BB - 1)];
    if (j < 56) { h_s[0][j] = 0.0f; h_s[1][j] = 0.0f; }

    // Two weight rows per thread, packed f32x2. Fold the sigmoid's 1/2
    // argument scaling into weights/bias so activation is bare tanh + fma.
    ull wpA[25], wpB[25];
    float bsumA, bsumB, wihA, wihB;
    {
        const ull* ra = reinterpret_cast<const ull*>(W_hh + rowA * HH);
        const ull* rb = reinterpret_cast<const ull*>(W_hh + rowB * HH);
        const ull s05 = pack2(0.5f, 0.5f);
        const ull sB  = half ? s05 : pack2(1.0f, 1.0f);
        #pragma unroll
        for (int k = 0; k < 25; k++) {
            wpA[k] = fmul2(ra[k], s05);   // rowA always sigmoid
            wpB[k] = fmul2(rb[k], sB);    // rowB sigmoid only on odd lanes
        }
        bsumA = 0.5f * (b_ih[rowA] + b_hh[rowA]);
        wihA  = 0.5f * W_ih[rowA];
        float sb = half ? 0.5f : 1.0f;
        bsumB = sb * (b_ih[rowB] + b_hh[rowB]);
        wihB  = sb * W_ih[rowB];
    }
    const float amulB = half ? 0.5f : 1.0f;   // post-tanh finish for rowB
    const float aaddB = half ? 0.5f : 0.0f;

    float c = 0.0f;   // redundant in both lanes of the pair (bit-identical)
    __syncthreads();

    #pragma unroll 1
    for (int t2 = 0; t2 < TT; t2 += 2) {
        #pragma unroll
        for (int s = 0; s < 2; s++) {
            const int t = t2 + s;
            const float* hsrc = h_s[s];
            float*       hdst = h_s[s ^ 1];
            const float  xv   = xcol[t];
            const float preA0 = fmaf(xv, wihA, bsumA);
            const float preB0 = fmaf(xv, wihB, bsumB);

            // --- two 50-dots sharing one h load; 4 accumulators each ---
            ull aA0 = 0ull, aA1 = 0ull, aA2 = 0ull, aA3 = 0ull;
            ull aB0 = 0ull, aB1 = 0ull, aB2 = 0ull, aB3 = 0ull;
            const ulonglong2* h4 = reinterpret_cast<const ulonglong2*>(hsrc);
            #pragma unroll
            for (int k = 0; k < 6; k++) {            // 24 packed pairs
                ulonglong2 p0 = h4[2 * k];
                ulonglong2 p1 = h4[2 * k + 1];
                aA0 = ffma2(wpA[4 * k],     p0.x, aA0);
                aA1 = ffma2(wpA[4 * k + 1], p0.y, aA1);
                aA2 = ffma2(wpA[4 * k + 2], p1.x, aA2);
                aA3 = ffma2(wpA[4 * k + 3], p1.y, aA3);
                aB0 = ffma2(wpB[4 * k],     p0.x, aB0);
                aB1 = ffma2(wpB[4 * k + 1], p0.y, aB1);
                aB2 = ffma2(wpB[4 * k + 2], p1.x, aB2);
                aB3 = ffma2(wpB[4 * k + 3], p1.y, aB3);
            }
            {
                ull hl = reinterpret_cast<const ull*>(hsrc)[24];  // pair 24
                aA0 = ffma2(wpA[24], hl, aA0);
                aB0 = ffma2(wpB[24], hl, aB0);
            }
            ull rA = fadd2(fadd2(aA0, aA1), fadd2(aA2, aA3));
            ull rB = fadd2(fadd2(aB0, aB1), fadd2(aB2, aB3));
            float preA = preA0 + (f2lo(rA) + f2hi(rA));
            float preB = preB0 + (f2lo(rB) + f2hi(rB));

            // --- activations (arg scaling pre-folded) ---
            float aAv = fmaf(tanh_fast(preA), 0.5f, 0.5f);     // i / f
            float aBv = fmaf(tanh_fast(preB), amulB, aaddB);   // g / o

            // --- R7-style gate exchange: two INDEPENDENT xor-1 shuffles ---
            float pown = aAv * aBv;           // = i*g on even lanes
            float s1 = __shfl_xor_sync(0xffffffffu, half ? aAv : pown, 1, 32);
            float s2 = __shfl_xor_sync(0xffffffffu, half ? aBv : pown, 1, 32);
            // even: f=s1, o=s2, p=pown ; odd: p=s1, f=aAv, o=aBv
            float fv = half ? aAv : s1;
            float ov = half ? aBv : s2;
            float pv = half ? s1  : pown;

            // --- redundant cell/hidden update (bit-identical both lanes) ---
            c = fmaf(fv, c, pv);
            float hn = ov * tanh_fast(c);
            if (u < HH) {
                if (!half) hdst[u] = hn;           // even lane: critical STS
                else       g_hs[t * HH + u] = hn;  // odd lane: off-path STG
            }
            __syncthreads();
        }
    }

    // Epilogue: out[t] = dot(h_t, W_lin) + b_lin, parallel over t.
    const float bl = b_lin[0];
    for (int t = j; t < TT; t += NTHREADS) {
        float s = bl;
        #pragma unroll
        for (int k = 0; k < HH; k++) s += g_hs[t * HH + k] * W_lin[k];
        out[t] = s;
    }
}

extern "C" void kernel_launch(void* const* d_in, const int* in_sizes, int n_in,
                              void* d_out, int out_size) {
    const float* x     = (const float*)d_in[0];
    const float* W_ih  = (const float*)d_in[1];
    const float* W_hh  = (const float*)d_in[2];
    const float* b_ih  = (const float*)d_in[3];
    const float* b_hh  = (const float*)d_in[4];
    const float* W_lin = (const float*)d_in[5];
    const float* b_lin = (const float*)d_in[6];
    lstm_seq_kernel<<<1, NTHREADS>>>(x, W_ih, W_hh, b_ih, b_hh, W_lin, b_lin,
                                     (float*)d_out);
}

// round 11
// speedup vs baseline: 1.1906x; 1.0808x over previous
#include <cuda_runtime.h>

// T=2048, B=1024, H=50, 4H=200. Only batch row B-1 reaches the output
// (reference takes hs[:, -1, :] on the batch axis) and the recurrence is
// batch-independent -> single length-2048 sequence, H=50, on ONE SM.
#define TT 2048
#define BB 1024
#define HH 50
#define NTHREADS 128   // 4 warps, 1 per SMSP; lane pair 2u/2u+1 owns unit u

// Per-timestep hidden history; output dot handled in parallel epilogue.
__device__ float g_hs[TT * HH];

typedef unsigned long long ull;

__device__ __forceinline__ ull ffma2(ull a, ull b, ull c) {
    ull d;
    asm("fma.rn.f32x2 %0, %1, %2, %3;" : "=l"(d) : "l"(a), "l"(b), "l"(c));
    return d;
}
__device__ __forceinline__ float tanh_fast(float x) {
    float r;
    asm("tanh.approx.f32 %0, %1;" : "=f"(r) : "f"(x));
    return r;
}
__device__ __forceinline__ float f2lo(ull v) { union { ull u; float2 f; } w; w.u = v; return w.f.x; }
__device__ __forceinline__ float f2hi(ull v) { union { ull u; float2 f; } w; w.u = v; return w.f.y; }

__global__ __launch_bounds__(NTHREADS, 1)
void lstm_seq_kernel(const float* __restrict__ x,      // (T, B, 1)
                     const float* __restrict__ W_ih,   // (4H, 1)
                     const float* __restrict__ W_hh,   // (4H, H)
                     const float* __restrict__ b_ih,
                     const float* __restrict__ b_hh,
                     const float* __restrict__ W_lin,  // (1, H)
                     const float* __restrict__ b_lin,
                     float* __restrict__ out)          // T floats
{
    __shared__ __align__(16) float h_s[2][56];  // double buffer; [50..55] pad
    __shared__ float xcol[TT + 1];              // +1 so prefetch never OOB

    const int j    = threadIdx.x;
    const int half = j & 1;                 // 0: gates (i,g)   1: gates (f,o)
    const int u    = j >> 1;                // unit 0..63 (>=50 redundant)
    const int uc   = (u < HH) ? u : (HH - 1);
    // rowA: i (even) / f (odd) -- always sigmoid
    // rowB: g (even, tanh) / o (odd, sigmoid)
    const int rowA = half ? (HH + uc)     : uc;
    const int rowB = half ? (3 * HH + uc) : (2 * HH + uc);

    for (int t = j; t < TT; t += NTHREADS) xcol[t] = x[t * BB + (BB - 1)];
    if (j == 0) xcol[TT] = 0.0f;
    if (j < 56) { h_s[0][j] = 0.0f; h_s[1][j] = 0.0f; }

    // Two weight rows per thread, packed f32x2 (row byte offset row*200, 8B ok)
    ull wpA[25], wpB[25];
    {
        const ull* ra = reinterpret_cast<const ull*>(W_hh + rowA * HH);
        const ull* rb = reinterpret_cast<const ull*>(W_hh + rowB * HH);
        #pragma unroll
        for (int k = 0; k < 25; k++) { wpA[k] = ra[k]; wpB[k] = rb[k]; }
    }
    const float bsumA = b_ih[rowA] + b_hh[rowA];
    const float bsumB = b_ih[rowB] + b_hh[rowB];
    const float wihA  = W_ih[rowA];
    const float wihB  = W_ih[rowB];
    // activation constants for rowB: tanh (even) vs sigmoid (odd)
    const float ascB  = half ? 0.5f : 1.0f;
    const float amulB = half ? 0.5f : 1.0f;
    const float aaddB = half ? 0.5f : 0.0f;

    float c = 0.0f;                 // redundant, bit-identical in both lanes
    float* gp = g_hs + uc;          // hoisted history pointer (odd lanes use)
    __syncthreads();

    float xv = xcol[0];             // x prefetched before each barrier

    #pragma unroll 1
    for (int t2 = 0; t2 < TT; t2 += 2) {
        #pragma unroll
        for (int s = 0; s < 2; s++) {
            const int t = t2 + s;
            const float* hsrc = h_s[s];
            float*       hdst = h_s[s ^ 1];
            const float preA0 = fmaf(xv, wihA, bsumA);
            const float preB0 = fmaf(xv, wihB, bsumB);

            // --- two 50-dots sharing one h load (12 LDS.128 + 1 LDS.64) ---
            ull aA0 = 0ull, aA1 = 0ull, aB0 = 0ull, aB1 = 0ull;
            const ulonglong2* h4 = reinterpret_cast<const ulonglong2*>(hsrc);
            #pragma unroll
            for (int k = 0; k < 12; k++) {
                ulonglong2 p = h4[k];
                aA0 = ffma2(wpA[2 * k],     p.x, aA0);
                aA1 = ffma2(wpA[2 * k + 1], p.y, aA1);
                aB0 = ffma2(wpB[2 * k],     p.x, aB0);
                aB1 = ffma2(wpB[2 * k + 1], p.y, aB1);
            }
            {
                ull hl = reinterpret_cast<const ull*>(hsrc)[24];
                aA0 = ffma2(wpA[24], hl, aA0);
                aB0 = ffma2(wpB[24], hl, aB0);
            }
            union { ull uv; float2 f; } uA0, uA1, uB0, uB1;
            uA0.uv = aA0; uA1.uv = aA1; uB0.uv = aB0; uB1.uv = aB1;
            float preA = preA0 + ((uA0.f.x + uA1.f.x) + (uA0.f.y + uA1.f.y));
            float preB = preB0 + ((uB0.f.x + uB1.f.x) + (uB0.f.y + uB1.f.y));

            // --- activations: sigmoid = 0.5 + 0.5*tanh(x/2) ---
            float aAv = fmaf(tanh_fast(preA * 0.5f), 0.5f, 0.5f);     // i / f
            float aBv = fmaf(tanh_fast(preB * ascB), amulB, aaddB);   // g / o

            // --- two INDEPENDENT xor-1 shuffles exchange gates in-pair ---
            float pown = aAv * aBv;           // = i*g on even lanes
            float s1 = __shfl_xor_sync(0xffffffffu, half ? aAv : pown, 1, 32);
            float s2 = __shfl_xor_sync(0xffffffffu, half ? aBv : pown, 1, 32);
            // even: f=s1, o=s2, p=pown ; odd: p=s1, f=aAv, o=aBv
            float fv = half ? aAv : s1;
            float ov = half ? aBv : s2;
            float pv = half ? s1  : pown;

            // --- redundant cell/hidden update (bit-identical both lanes) ---
            c = fmaf(fv, c, pv);
            float hn = ov * tanh_fast(c);
            // Branchless stores: redundant lanes (u>=50) clamp to uc=49 and
            // write the SAME value -> benign, deterministic.
            if (!half) hdst[uc] = hn;          // even lane: critical STS
            else       gp[t * HH] = hn;        // odd lane: off-path STG

            xv = xcol[t + 1];                  // prefetch next x pre-barrier
            __syncthreads();
        }
    }

    // Epilogue: out[t] = dot(h_t, W_lin) + b_lin, parallel over t.
    const float bl = b_lin[0];
    for (int t = j; t < TT; t += NTHREADS) {
        float s = bl;
        #pragma unroll
        for (int k = 0; k < HH; k++) s += g_hs[t * HH + k] * W_lin[k];
        out[t] = s;
    }
}

extern "C" void kernel_launch(void* const* d_in, const int* in_sizes, int n_in,
                              void* d_out, int out_size) {
    const float* x     = (const float*)d_in[0];
    const float* W_ih  = (const float*)d_in[1];
    const float* W_hh  = (const float*)d_in[2];
    const float* b_ih  = (const float*)d_in[3];
    const float* b_hh  = (const float*)d_in[4];
    const float* W_lin = (const float*)d_in[5];
    const float* b_lin = (const float*)d_in[6];
    lstm_seq_kernel<<<1, NTHREADS>>>(x, W_ih, W_hh, b_ih, b_hh, W_lin, b_lin,
                                     (float*)d_out);
}